// round 15
// baseline (speedup 1.0000x reference)
#include <cuda_runtime.h>
#include <cuda_fp16.h>
#include <cstdint>
#include <math.h>

#define NCTA 128
#define NTH  512
#define HDIM 512
#define BD   128
#define TENC 512
#define PRED 32
#define HB   (HDIM * BD)   // floats per h slab

typedef unsigned long long ull;
typedef unsigned int u32;

// ---------------- device scratch (static, no allocation) ----------------
__device__ float  g_hist[(size_t)(TENC + 1) * HB];   // fp32 h history, slab 0 = h0 (134.5MB)
__device__ __half g_ench[(size_t)TENC * HB];         // fp16 enc outputs [t][j][b] (67MB)
__device__ float  g_h[2][HB];                        // decoder RNN hidden ping-pong
__device__ float  g_p[TENC * BD];                    // p[t][b] = enc_t[b] . lin_W
__device__ float  g_sc[TENC * BD];                   // attention scores [t][b]
__device__ float  g_x[BD];                           // decoder input x[b]
__device__ volatile unsigned g_gen = 0;
__device__ unsigned g_cnt = 0;

// ---------------- helpers ----------------
__device__ __forceinline__ void fma2(ull& d, ull a, ull b) {
    asm("fma.rn.f32x2 %0, %1, %2, %0;" : "+l"(d) : "l"(a), "l"(b));
}
__device__ __forceinline__ ull pk(float a, float b) {
    ull r; asm("mov.b64 %0, {%1, %2};" : "=l"(r) : "f"(a), "f"(b)); return r;
}
__device__ __forceinline__ float2 upk(ull v) {
    float2 r; asm("mov.b64 {%0, %1}, %2;" : "=f"(r.x), "=f"(r.y) : "l"(v)); return r;
}
__device__ __forceinline__ float sigf(float x) { return 1.0f / (1.0f + expf(-x)); }

__device__ __forceinline__ void cpasync16(u32 smem_dst, const void* gsrc) {
    asm volatile("cp.async.cg.shared.global [%0], [%1], 16;\n"
                 :: "r"(smem_dst), "l"(gsrc) : "memory");
}
__device__ __forceinline__ void cpcommit() {
    asm volatile("cp.async.commit_group;\n" ::: "memory");
}
__device__ __forceinline__ void cpwait1() {
    asm volatile("cp.async.wait_group 1;\n" ::: "memory");
}
__device__ __forceinline__ void cpwait0() {
    asm volatile("cp.async.wait_group 0;\n" ::: "memory");
}
__device__ __forceinline__ void barpair(int id) {
    asm volatile("bar.sync %0, 64;\n" :: "r"(id) : "memory");
}

// Software grid barrier: 128 CTAs, 1/SM, all co-resident. (Proven R10-R13.)
__device__ __forceinline__ void grid_sync() {
    __syncthreads();
    if (threadIdx.x == 0) {
        __threadfence();
        unsigned gen = g_gen;
        if (atomicAdd(&g_cnt, 1u) == NCTA - 1u) {
            g_cnt = 0u;
            __threadfence();
            g_gen = gen + 1u;
        } else {
            while (g_gen == gen) { __nanosleep(32); }
        }
        __threadfence();
    }
    __syncthreads();
}

// SMEM layout (dynamic, 145536 B):
//   Wd 64K | psum/stage union 64K | gsm 8K | c_s 2K | bias 64 | wih 64 | red 4K
// psum/stage union: each kseg owns bytes [kseg*8192, kseg*8192+8192):
//   during matvec  : two 4KB h-stage buffers (chunk parity c&1)
//   after matvec   : its psum rows (kseg*16 .. kseg*16+15), same bytes
#define SMEM_BYTES (65536 + 65536 + 8192 + 2048 + 64 + 64 + 4096)

__global__ void __launch_bounds__(NTH, 1)
lstm_attn_kernel(const float* __restrict__ inseq,
                 const float* __restrict__ h0,   const float* __restrict__ c0,
                 const float* __restrict__ Wih,  const float* __restrict__ Whh,
                 const float* __restrict__ bih,  const float* __restrict__ bhh,
                 const float* __restrict__ rWih, const float* __restrict__ rWhh,
                 const float* __restrict__ rbih, const float* __restrict__ rbhh,
                 const float* __restrict__ linW, const float* __restrict__ linb,
                 float* __restrict__ dout)
{
    extern __shared__ char smem_raw[];
    ull*        Wd     = reinterpret_cast<ull*>(smem_raw);
    char*       stage  = smem_raw + 65536;                       // union w/ psum
    ull*        psum   = reinterpret_cast<ull*>(stage);
    ulonglong2* psum2  = reinterpret_cast<ulonglong2*>(psum);
    float*      psum_f = reinterpret_cast<float*>(psum);
    float*      gsm    = reinterpret_cast<float*>(smem_raw + 131072);
    float*      c_s    = gsm + 2048;
    float*      bias_s = c_s + 512;
    float*      wih_s  = bias_s + 16;
    float*      red    = wih_s + 16;
    float2*     red2   = reinterpret_cast<float2*>(red);

    const int g    = blockIdx.x;
    const int tid  = threadIdx.x;
    const int lane = tid & 31;
    const int wrp  = tid >> 5;
    const int kseg = wrp & 7;     // k segment [64*kseg, 64*kseg+64)
    const int rhalf= wrp >> 3;    // rows rhalf*8 .. rhalf*8+7

    const u32 stage_u32 =
        (u32)__cvta_generic_to_shared(stage) + kseg * 8192;

    // ---- encoder weights: Wd[k][16] with r = gate*4 + jj ----
    for (int idx = tid; idx < 16 * HDIM; idx += NTH) {
        int k = idx >> 4, r = idx & 15;
        int gi = r >> 2, jj = r & 3;
        float w = Whh[(size_t)(gi * HDIM + 4 * g + jj) * HDIM + k];
        Wd[k * 16 + r] = pk(w, w);
    }
    if (tid < 16) {
        int gi = tid >> 2, jj = tid & 3;
        int row = gi * HDIM + 4 * g + jj;
        bias_s[tid] = bih[row] + bhh[row];
        wih_s[tid]  = Wih[row];            // I == 1
    }
    for (int q = tid; q < 512; q += NTH) {
        int jj = q >> 7, b = q & 127;
        c_s[q] = c0[b * HDIM + 4 * g + jj];
        g_hist[(4 * g + jj) * BD + b] = h0[b * HDIM + 4 * g + jj];  // slab 0
    }
    grid_sync();

    // ======================= encoder: 512 LSTM steps =======================
    for (int t = 0; t < TENC; ++t) {
        // h source for this kseg: rows k = kseg*64 + (c*8 + klocal)
        const float* hsrc = g_hist + (size_t)t * HB + (kseg * 64) * BD;
        const ulonglong2* wseg =
            reinterpret_cast<const ulonglong2*>(Wd + (kseg * 64) * 16) + rhalf * 4;
        const float* stage_f = reinterpret_cast<const float*>(stage + kseg * 8192);

        ull acc[8][2];
        #pragma unroll
        for (int r = 0; r < 8; ++r) { acc[r][0] = 0ull; acc[r][1] = 0ull; }

        // issue chunk 0: this warp copies klocal = rhalf*4 .. rhalf*4+3
        {
            u32 dst = stage_u32 + (rhalf * 4) * 512 + lane * 16;
            const float* src = hsrc + (rhalf * 4) * BD + lane * 4;
            #pragma unroll
            for (int i = 0; i < 4; ++i)
                cpasync16(dst + i * 512, src + i * BD);
            cpcommit();
        }

        #pragma unroll
        for (int c = 0; c < 8; ++c) {
            // prefetch chunk c+1 into the other buffer
            if (c < 7) {
                u32 dst = stage_u32 + ((c + 1) & 1) * 4096
                        + (rhalf * 4) * 512 + lane * 16;
                const float* src = hsrc + ((c + 1) * 8 + rhalf * 4) * BD + lane * 4;
                #pragma unroll
                for (int i = 0; i < 4; ++i)
                    cpasync16(dst + i * 512, src + i * BD);
                cpcommit();
            }
            if (c < 7) cpwait1(); else cpwait0();   // chunk c landed
            barpair(1 + kseg);                       // twin warp's half too

            // compute 8 k's of chunk c from SMEM buffer (c&1)
            const float* hb = stage_f + (c & 1) * 1024;   // floats
            const ulonglong2* wp = wseg + (c * 8) * 8;
            #pragma unroll
            for (int j = 0; j < 8; ++j) {
                ulonglong2 h2 = *reinterpret_cast<const ulonglong2*>(hb + j * 128 + lane * 4);
                ull hx = h2.x, hy = h2.y;
                #pragma unroll
                for (int i = 0; i < 4; ++i) {
                    ulonglong2 w = wp[j * 8 + i];        // rows 2i,2i+1 (dup format)
                    fma2(acc[2*i  ][0], w.x, hx); fma2(acc[2*i  ][1], w.x, hy);
                    fma2(acc[2*i+1][0], w.y, hx); fma2(acc[2*i+1][1], w.y, hy);
                }
            }
        }
        barpair(1 + kseg);   // twin must finish reading buf1 before psum writes

        // prefetch input x for phase1
        float xv = inseq[t * BD + (tid & 127)];

        // partials -> SMEM (same bytes as stage, now safe)
        #pragma unroll
        for (int r = 0; r < 8; ++r) {
            psum2[(kseg * 16 + rhalf * 8 + r) * 32 + lane] =
                make_ulonglong2(acc[r][0], acc[r][1]);
        }
        __syncthreads();
        // --- phase1: sum 8 k-segments + input/bias -> gates gsm[row*128+b] ---
        #pragma unroll
        for (int i = 0; i < 4; ++i) {
            int q = tid + i * NTH;               // q = row*128 + b
            int row = q >> 7;
            float s = psum_f[q]          + psum_f[2048 + q]
                    + psum_f[2*2048 + q] + psum_f[3*2048 + q]
                    + psum_f[4*2048 + q] + psum_f[5*2048 + q]
                    + psum_f[6*2048 + q] + psum_f[7*2048 + q];
            gsm[q] = s + xv * wih_s[row] + bias_s[row];
        }
        __syncthreads();
        // --- phase2: LSTM cell update + write h (fp32 history + fp16 copy) ---
        {
            int q = tid;                          // exactly 512 cells
            int jj = q >> 7, b = q & 127;
            float ig = sigf (gsm[( 0 + jj) * BD + b]);
            float fg = sigf (gsm[( 4 + jj) * BD + b]);
            float gg = tanhf(gsm[( 8 + jj) * BD + b]);
            float og = sigf (gsm[(12 + jj) * BD + b]);
            float c = fg * c_s[q] + ig * gg;
            float h = og * tanhf(c);
            c_s[q] = c;
            g_hist[(size_t)(t + 1) * HB + (4 * g + jj) * BD + b] = h;
            g_ench[(size_t)t * HB + (4 * g + jj) * BD + b] = __float2half(h);
        }
        grid_sync();
    }

    // ======= precompute p[t][b] = enc_t[b].linW (fp16 enc); x0; dec weights =======
    for (int idx = tid; idx < HDIM; idx += NTH) gsm[idx] = linW[idx];
    __syncthreads();
    for (int tt = 0; tt < 4; ++tt) {
        int t = g + tt * NCTA;
        int b2 = tid & 63, hf = tid >> 6;   // 8 chunks of 64 j-rows
        const __half2* ep = reinterpret_cast<const __half2*>(g_ench + (size_t)t * HB)
                            + (hf * 64) * 64 + b2;
        float2 a = make_float2(0.0f, 0.0f);
        #pragma unroll 4
        for (int j = 0; j < 64; ++j) {
            float2 hv = __half22float2(ep[j * 64]);
            float lw = gsm[hf * 64 + j];
            a.x += hv.x * lw; a.y += hv.y * lw;
        }
        red2[hf * 64 + b2] = a;
        __syncthreads();
        if (hf == 0) {
            float sx = 0.0f, sy = 0.0f;
            #pragma unroll
            for (int c = 0; c < 8; ++c) { float2 r = red2[c * 64 + b2]; sx += r.x; sy += r.y; }
            g_p[t * BD + 2 * b2]     = sx;
            g_p[t * BD + 2 * b2 + 1] = sy;
        }
        __syncthreads();
    }
    if (g == 0 && tid < BD) g_x[tid] = inseq[TENC * BD + tid];  // x0 = input_seq[-1]
    // decoder weights: Wd[lr][k] (w,w)-dup, lr = 0..3 (rows 4g..4g+3)
    for (int idx = tid; idx < 4 * HDIM; idx += NTH) {
        int lr = idx >> 9, k = idx & (HDIM - 1);
        float w = rWhh[(size_t)(4 * g + lr) * HDIM + k];
        Wd[lr * HDIM + k] = pk(w, w);
    }
    if (tid < 4) {
        int row = 4 * g + tid;
        bias_s[tid] = rbih[row] + rbhh[row];
        wih_s[tid]  = rWih[row];           // O == 1
    }
    grid_sync();

    // ======================= decoder: 32 steps =======================
    int cur = 0;
    for (int s = 0; s < PRED; ++s) {
        const int nxt = cur ^ 1;
        // --- RNN matvec (256 threads): h_new = tanh(x*rWih + rb + rWhh.h_old) ---
        if (tid < 256) {
            int jj = tid >> 6, bb = tid & 63;
            ull acc = 0ull;
            const float* hb = (s == 0) ? (g_hist + (size_t)TENC * HB) : g_h[cur];
            const ull*   wp = Wd + jj * HDIM;
            #pragma unroll 4
            for (int k = 0; k < HDIM; ++k) {
                double hv = __ldcg(reinterpret_cast<const double*>(hb + k * BD + bb * 2));
                fma2(acc, wp[k], (ull)__double_as_longlong(hv));
            }
            float2 f = upk(acc);
            float rwi = wih_s[jj], rb = bias_s[jj];
            int b0 = 2 * bb;
            float x0v = __ldcg(g_x + b0), x1v = __ldcg(g_x + b0 + 1);
            __stcg(&g_h[nxt][(4 * g + jj) * BD + b0],     tanhf(f.x + x0v * rwi + rb));
            __stcg(&g_h[nxt][(4 * g + jj) * BD + b0 + 1], tanhf(f.y + x1v * rwi + rb));
        }
        grid_sync();
        // --- scores[t][b] = enc_t[b] . h_new[b], enc fp16 (L2-resident) ---
        for (int tt = 0; tt < 4; ++tt) {
            int t = g + tt * NCTA;
            int b2 = tid & 63, hf = tid >> 6;
            const __half2* ep = reinterpret_cast<const __half2*>(g_ench + (size_t)t * HB)
                                + (hf * 64) * 64 + b2;
            const float2* hp = reinterpret_cast<const float2*>(g_h[nxt]) + (hf * 64) * 64 + b2;
            float2 a = make_float2(0.0f, 0.0f);
            #pragma unroll 4
            for (int j = 0; j < 64; ++j) {
                float2 hv = __half22float2(ep[j * 64]);
                float2 hh = __ldcg(hp + j * 64);
                a.x += hv.x * hh.x; a.y += hv.y * hh.y;
            }
            red2[hf * 64 + b2] = a;
            __syncthreads();
            if (hf == 0) {
                float sx = 0.0f, sy = 0.0f;
                #pragma unroll
                for (int c = 0; c < 8; ++c) { float2 r = red2[c * 64 + b2]; sx += r.x; sy += r.y; }
                g_sc[t * BD + 2 * b2]     = sx;
                g_sc[t * BD + 2 * b2 + 1] = sy;
            }
            __syncthreads();
        }
        grid_sync();
        // --- softmax over t + output; CTA g owns batch element b = g ---
        {
            float s1 = __ldcg(g_sc + tid * BD + g);   // tid covers all 512 t
            red[tid] = s1;
            __syncthreads();
            for (int off = 256; off > 0; off >>= 1) {
                if (tid < off) red[tid] = fmaxf(red[tid], red[tid + off]);
                __syncthreads();
            }
            float mall = red[0];
            __syncthreads();
            float e1 = expf(s1 - mall);
            float wp1 = e1 * g_p[tid * BD + g];
            red[tid] = e1;
            gsm[tid] = wp1;
            __syncthreads();
            for (int off = 256; off > 0; off >>= 1) {
                if (tid < off) { red[tid] += red[tid + off]; gsm[tid] += gsm[tid + off]; }
                __syncthreads();
            }
            if (tid == 0) {
                float o = fmaxf(0.0f, gsm[0] / red[0] + linb[0]);
                dout[s * BD + g] = o;
                __stcg(&g_x[g], o);
            }
        }
        grid_sync();
        cur = nxt;
    }
}

extern "C" void kernel_launch(void* const* d_in, const int* in_sizes, int n_in,
                              void* d_out, int out_size) {
    (void)in_sizes; (void)n_in; (void)out_size;
    cudaFuncSetAttribute(lstm_attn_kernel,
                         cudaFuncAttributeMaxDynamicSharedMemorySize, SMEM_BYTES);
    const float* inseq = (const float*)d_in[0];
    const float* h0    = (const float*)d_in[1];
    const float* c0    = (const float*)d_in[2];
    const float* Wih   = (const float*)d_in[3];
    const float* Whh   = (const float*)d_in[4];
    const float* bih   = (const float*)d_in[5];
    const float* bhh   = (const float*)d_in[6];
    const float* rWih  = (const float*)d_in[7];
    const float* rWhh  = (const float*)d_in[8];
    const float* rbih  = (const float*)d_in[9];
    const float* rbhh  = (const float*)d_in[10];
    const float* linW  = (const float*)d_in[11];
    const float* linb  = (const float*)d_in[12];
    float* dout = (float*)d_out;
    lstm_attn_kernel<<<NCTA, NTH, SMEM_BYTES>>>(
        inseq, h0, c0, Wih, Whh, bih, bhh,
        rWih, rWhh, rbih, rbhh, linW, linb, dout);
}